// round 1
// baseline (speedup 1.0000x reference)
#include <cuda_runtime.h>
#include <math.h>

#define BB 4
#define SS 2048
#define HH 16
#define DKK 64
#define DMODEL 1024
#define MTOT (BB*SS)   // 8192

// Scratch (device globals: no allocation allowed)
__device__ float g_q[BB*HH*SS*DKK];     // [B,H,S,Dk]
__device__ float g_k[BB*HH*SS*DKK];
__device__ float g_v[BB*HH*SS*DKK];
__device__ float g_att[BB*SS*DMODEL];   // [B,S,Dmodel]

// ---------------------------------------------------------------------------
// GEMM: Y = X(MxK) @ W^T (W is NxK, row-major) + bias
// MODE 0: write Y permuted to [B,H,S,Dk]   (n = h*64+d, m = b*S+s)
// MODE 1: write Y plain [M,N]
// Block 128x128, BK=8, 256 threads, 8x8 per-thread microtile.
// ---------------------------------------------------------------------------
template<int MODE>
__global__ __launch_bounds__(256) void gemm_bias_kernel(
    const float* __restrict__ X, const float* __restrict__ W,
    const float* __restrict__ bias, float* __restrict__ Y,
    int M, int N, int K)
{
    __shared__ float As[8][128];
    __shared__ float Bs[8][128];

    const int tid = threadIdx.x;
    const int m0 = blockIdx.y * 128;
    const int n0 = blockIdx.x * 128;
    const int ty = tid >> 4;        // 0..15
    const int tx = tid & 15;        // 0..15

    const int lr = tid >> 1;        // 0..127  (row within tile for loads)
    const int lk = (tid & 1) * 4;   // 0 or 4  (k offset for loads)

    const float* Xp = X + (long)(m0 + lr) * K + lk;
    const float* Wp = W + (long)(n0 + lr) * K + lk;

    float acc[8][8];
    #pragma unroll
    for (int i = 0; i < 8; i++)
        #pragma unroll
        for (int j = 0; j < 8; j++) acc[i][j] = 0.f;

    for (int k0 = 0; k0 < K; k0 += 8) {
        float4 xa = *(const float4*)(Xp + k0);
        float4 wb = *(const float4*)(Wp + k0);
        As[lk+0][lr] = xa.x; As[lk+1][lr] = xa.y;
        As[lk+2][lr] = xa.z; As[lk+3][lr] = xa.w;
        Bs[lk+0][lr] = wb.x; Bs[lk+1][lr] = wb.y;
        Bs[lk+2][lr] = wb.z; Bs[lk+3][lr] = wb.w;
        __syncthreads();

        #pragma unroll
        for (int kk = 0; kk < 8; kk++) {
            float a[8], b[8];
            #pragma unroll
            for (int i = 0; i < 8; i++) a[i] = As[kk][ty*8 + i];
            #pragma unroll
            for (int j = 0; j < 8; j++) b[j] = Bs[kk][tx*8 + j];
            #pragma unroll
            for (int i = 0; i < 8; i++)
                #pragma unroll
                for (int j = 0; j < 8; j++)
                    acc[i][j] += a[i] * b[j];
        }
        __syncthreads();
    }

    // Epilogue: bias + store
    #pragma unroll
    for (int i = 0; i < 8; i++) {
        int m = m0 + ty*8 + i;
        #pragma unroll
        for (int j = 0; j < 8; j++) {
            int n = n0 + tx*8 + j;
            float v = acc[i][j] + bias[n];
            if (MODE == 0) {
                int b_ = m >> 11;          // /S
                int s_ = m & (SS - 1);
                int h_ = n >> 6;           // /Dk
                int d_ = n & 63;
                g_nop:;
                ((float*)Y)[(((long)(b_*HH + h_)) * SS + s_) * DKK + d_] = v;
            } else {
                Y[(long)m * N + n] = v;
            }
        }
    }
}

// ---------------------------------------------------------------------------
// Flash attention: one block per (b*h, 64-query tile).
// 256 threads as 16x16 grid; 4x4 microtile over the 64x64 score tile.
// Online softmax over key chunks of 64.
// Q,K,V in [B,H,S,Dk] layout. Output to g_att [B,S,Dmodel].
// ---------------------------------------------------------------------------
#define QT 64
#define KT 64
#define PADS 65
#define SMEM_ATT (4 * QT * PADS * 4)   // Qs, Ks, Vs, Ps -> 66560 bytes

__global__ __launch_bounds__(256) void attention_kernel(
    const float* __restrict__ Q, const float* __restrict__ K,
    const float* __restrict__ V, float* __restrict__ O)
{
    extern __shared__ float sm[];
    float* Qs = sm;                  // [64][65]
    float* Ks = Qs + QT * PADS;
    float* Vs = Ks + KT * PADS;
    float* Ps = Vs + KT * PADS;

    const int tid = threadIdx.x;
    const int ty = tid >> 4;         // 0..15
    const int tx = tid & 15;         // 0..15
    const int q0 = blockIdx.x * QT;  // query tile start
    const int bh = blockIdx.y;       // 0..63

    const float* Qg = Q + ((long)bh * SS + q0) * DKK;
    const float* Kg = K + (long)bh * SS * DKK;
    const float* Vg = V + (long)bh * SS * DKK;

    // Load Q tile (64x64)
    for (int t = tid; t < QT * DKK / 4; t += 256) {
        int row = t >> 4;
        int c4  = (t & 15) * 4;
        float4 v4 = *(const float4*)(Qg + row * DKK + c4);
        Qs[row*PADS + c4+0] = v4.x; Qs[row*PADS + c4+1] = v4.y;
        Qs[row*PADS + c4+2] = v4.z; Qs[row*PADS + c4+3] = v4.w;
    }

    float m_i[4], l_i[4], o[4][4];
    #pragma unroll
    for (int i = 0; i < 4; i++) {
        m_i[i] = -1e30f; l_i[i] = 0.f;
        #pragma unroll
        for (int j = 0; j < 4; j++) o[i][j] = 0.f;
    }

    for (int kc = 0; kc < SS; kc += KT) {
        __syncthreads();   // prior iteration done reading Ks/Vs/Ps; Q load visible
        // Load K,V chunk (64x64 each)
        for (int t = tid; t < KT * DKK / 4; t += 256) {
            int row = t >> 4;
            int c4  = (t & 15) * 4;
            float4 kv = *(const float4*)(Kg + (long)(kc + row) * DKK + c4);
            Ks[row*PADS + c4+0] = kv.x; Ks[row*PADS + c4+1] = kv.y;
            Ks[row*PADS + c4+2] = kv.z; Ks[row*PADS + c4+3] = kv.w;
            float4 vv = *(const float4*)(Vg + (long)(kc + row) * DKK + c4);
            Vs[row*PADS + c4+0] = vv.x; Vs[row*PADS + c4+1] = vv.y;
            Vs[row*PADS + c4+2] = vv.z; Vs[row*PADS + c4+3] = vv.w;
        }
        __syncthreads();

        // Scores S = Q K^T * (1/8)
        float s[4][4];
        #pragma unroll
        for (int i = 0; i < 4; i++)
            #pragma unroll
            for (int j = 0; j < 4; j++) s[i][j] = 0.f;

        #pragma unroll 8
        for (int d = 0; d < DKK; d++) {
            float a[4], bq[4];
            #pragma unroll
            for (int i = 0; i < 4; i++) a[i]  = Qs[(ty*4 + i)*PADS + d];
            #pragma unroll
            for (int j = 0; j < 4; j++) bq[j] = Ks[(tx*4 + j)*PADS + d];
            #pragma unroll
            for (int i = 0; i < 4; i++)
                #pragma unroll
                for (int j = 0; j < 4; j++)
                    s[i][j] += a[i] * bq[j];
        }

        // Online softmax update (per 4 rows owned by this ty group)
        #pragma unroll
        for (int i = 0; i < 4; i++) {
            float lm = -1e30f;
            #pragma unroll
            for (int j = 0; j < 4; j++) {
                s[i][j] *= 0.125f;               // 1/sqrt(64)
                lm = fmaxf(lm, s[i][j]);
            }
            #pragma unroll
            for (int off = 8; off >= 1; off >>= 1)
                lm = fmaxf(lm, __shfl_xor_sync(0xffffffffu, lm, off));
            float nm   = fmaxf(m_i[i], lm);
            float corr = __expf(m_i[i] - nm);
            m_i[i] = nm;
            float rs = 0.f;
            #pragma unroll
            for (int j = 0; j < 4; j++) {
                float p = __expf(s[i][j] - nm);
                s[i][j] = p;
                rs += p;
            }
            #pragma unroll
            for (int off = 8; off >= 1; off >>= 1)
                rs += __shfl_xor_sync(0xffffffffu, rs, off);
            l_i[i] = l_i[i] * corr + rs;
            #pragma unroll
            for (int j = 0; j < 4; j++) o[i][j] *= corr;
            #pragma unroll
            for (int j = 0; j < 4; j++)
                Ps[(ty*4 + i)*PADS + tx*4 + j] = s[i][j];
        }
        __syncthreads();

        // O += P @ V
        #pragma unroll 8
        for (int j = 0; j < KT; j++) {
            float a[4], bv[4];
            #pragma unroll
            for (int i = 0; i < 4; i++)  a[i]  = Ps[(ty*4 + i)*PADS + j];
            #pragma unroll
            for (int jj = 0; jj < 4; jj++) bv[jj] = Vs[j*PADS + tx*4 + jj];
            #pragma unroll
            for (int i = 0; i < 4; i++)
                #pragma unroll
                for (int jj = 0; jj < 4; jj++)
                    o[i][jj] += a[i] * bv[jj];
        }
    }

    // Finalize and write to [B,S,Dmodel]
    const int b_ = bh >> 4;
    const int h_ = bh & 15;
    #pragma unroll
    for (int i = 0; i < 4; i++) {
        float inv = 1.f / l_i[i];
        int row = q0 + ty*4 + i;
        float4 v4;
        v4.x = o[i][0] * inv; v4.y = o[i][1] * inv;
        v4.z = o[i][2] * inv; v4.w = o[i][3] * inv;
        *(float4*)(O + ((long)b_ * SS + row) * DMODEL + h_ * DKK + tx * 4) = v4;
    }
}

// ---------------------------------------------------------------------------
extern "C" void kernel_launch(void* const* d_in, const int* in_sizes, int n_in,
                              void* d_out, int out_size)
{
    const float* query = (const float*)d_in[0];
    const float* key   = (const float*)d_in[1];
    const float* value = (const float*)d_in[2];
    const float* w_q   = (const float*)d_in[3];
    const float* b_q   = (const float*)d_in[4];
    const float* w_k   = (const float*)d_in[5];
    const float* b_k   = (const float*)d_in[6];
    const float* w_v   = (const float*)d_in[7];
    const float* b_v   = (const float*)d_in[8];
    const float* w_o   = (const float*)d_in[9];
    const float* b_o   = (const float*)d_in[10];
    float* out = (float*)d_out;

    float *q_buf, *k_buf, *v_buf, *att_buf;
    cudaGetSymbolAddress((void**)&q_buf,   g_q);
    cudaGetSymbolAddress((void**)&k_buf,   g_k);
    cudaGetSymbolAddress((void**)&v_buf,   g_v);
    cudaGetSymbolAddress((void**)&att_buf, g_att);

    cudaFuncSetAttribute(attention_kernel,
                         cudaFuncAttributeMaxDynamicSharedMemorySize, SMEM_ATT);

    dim3 gGemm(DMODEL / 128, MTOT / 128);   // (8, 64)

    gemm_bias_kernel<0><<<gGemm, 256>>>(query, w_q, b_q, q_buf, MTOT, DMODEL, DMODEL);
    gemm_bias_kernel<0><<<gGemm, 256>>>(key,   w_k, b_k, k_buf, MTOT, DMODEL, DMODEL);
    gemm_bias_kernel<0><<<gGemm, 256>>>(value, w_v, b_v, v_buf, MTOT, DMODEL, DMODEL);

    attention_kernel<<<dim3(SS / QT, BB * HH), 256, SMEM_ATT>>>(q_buf, k_buf, v_buf, att_buf);

    gemm_bias_kernel<1><<<gGemm, 256>>>(att_buf, w_o, b_o, out, MTOT, DMODEL, DMODEL);
}

// round 5
// speedup vs baseline: 5.0066x; 5.0066x over previous
#include <cuda_runtime.h>
#include <cuda_fp16.h>
#include <math.h>
#include <stdint.h>

#define BB 4
#define SS 2048
#define HH 16
#define DKK 64
#define DMODEL 1024
#define MTOT (BB*SS)   // 8192

// Scratch (device globals: no allocation allowed)
__device__ __half g_q[BB*HH*SS*DKK];    // [B,H,S,Dk] fp16
__device__ __half g_k[BB*HH*SS*DKK];
__device__ __half g_v[BB*HH*SS*DKK];
__device__ float  g_att[BB*SS*DMODEL];  // [B,S,Dmodel] fp32

// ---------------------------------------------------------------------------
// common mma/ldmatrix helpers
// ---------------------------------------------------------------------------
__device__ __forceinline__ uint32_t smem_u32(const void* p) {
    return (uint32_t)__cvta_generic_to_shared(p);
}
__device__ __forceinline__ void ldm_x4(uint32_t& r0, uint32_t& r1,
                                       uint32_t& r2, uint32_t& r3, uint32_t addr) {
    asm volatile("ldmatrix.sync.aligned.m8n8.x4.shared.b16 {%0,%1,%2,%3}, [%4];\n"
                 : "=r"(r0), "=r"(r1), "=r"(r2), "=r"(r3) : "r"(addr));
}
__device__ __forceinline__ void ldm_x4_t(uint32_t& r0, uint32_t& r1,
                                         uint32_t& r2, uint32_t& r3, uint32_t addr) {
    asm volatile("ldmatrix.sync.aligned.m8n8.x4.trans.shared.b16 {%0,%1,%2,%3}, [%4];\n"
                 : "=r"(r0), "=r"(r1), "=r"(r2), "=r"(r3) : "r"(addr));
}
__device__ __forceinline__ void mma16816(float* c, const uint32_t* a, const uint32_t* b) {
    asm volatile(
        "mma.sync.aligned.m16n8k16.row.col.f32.f16.f16.f32 "
        "{%0,%1,%2,%3}, {%4,%5,%6,%7}, {%8,%9}, {%0,%1,%2,%3};\n"
        : "+f"(c[0]), "+f"(c[1]), "+f"(c[2]), "+f"(c[3])
        : "r"(a[0]), "r"(a[1]), "r"(a[2]), "r"(a[3]), "r"(b[0]), "r"(b[1]));
}

// ---------------------------------------------------------------------------
// fp16 tensor-core GEMM:  Y = X(MxK) @ W^T (W is NxK row-major) + bias
// MODE 0: write __half Y permuted to [B,H,S,Dk]   (n = h*64+d, m = b*S+s)
// MODE 1: write float Y plain [M,N]
// Block 128x128, BK=32 halfs, 256 threads = 8 warps (2x4), warp tile 64x32.
// ---------------------------------------------------------------------------
#define BM 128
#define BN 128
#define BKH 32
#define PAD 40   // row stride in halfs (80B): conflict-free ldmatrix

__device__ __forceinline__ void sts_tile_f16(__half* dst, int lrow, int lcol,
                                             const float4* v) {
    #pragma unroll
    for (int t = 0; t < 4; t++) {
        half2 h0 = __floats2half2_rn(v[t].x, v[t].y);
        half2 h1 = __floats2half2_rn(v[t].z, v[t].w);
        __half* p = dst + lrow * PAD + lcol + 4 * t;
        *reinterpret_cast<half2*>(p)     = h0;
        *reinterpret_cast<half2*>(p + 2) = h1;
    }
}

template<int MODE>
__global__ __launch_bounds__(256) void gemm_mma_kernel(
    const float* __restrict__ X, const float* __restrict__ W,
    const float* __restrict__ bias, void* __restrict__ Yv,
    int M, int N, int K)
{
    __shared__ __half As[2][BM * PAD];
    __shared__ __half Bs[2][BN * PAD];

    const int tid  = threadIdx.x;
    const int lane = tid & 31;
    const int wid  = tid >> 5;
    const int wm   = (wid & 1) * 64;
    const int wn   = (wid >> 1) * 32;
    const int m0   = blockIdx.y * BM;
    const int n0   = blockIdx.x * BN;

    const int lrow = tid >> 1;
    const int lcol = (tid & 1) * 16;
    const float* Xp = X + (long)(m0 + lrow) * K + lcol;
    const float* Wp = W + (long)(n0 + lrow) * K + lcol;

    float acc[4][4][4];
    #pragma unroll
    for (int i = 0; i < 4; i++)
        #pragma unroll
        for (int j = 0; j < 4; j++)
            #pragma unroll
            for (int c = 0; c < 4; c++) acc[i][j][c] = 0.f;

    const int NT = K / BKH;

    float4 xa[4], wb[4];
    #pragma unroll
    for (int t = 0; t < 4; t++) {
        xa[t] = *(const float4*)(Xp + 4 * t);
        wb[t] = *(const float4*)(Wp + 4 * t);
    }
    sts_tile_f16(As[0], lrow, lcol, xa);
    sts_tile_f16(Bs[0], lrow, lcol, wb);
    __syncthreads();

    for (int kt = 0; kt < NT; kt++) {
        const int cur = kt & 1;
        if (kt + 1 < NT) {
            const float* Xn = Xp + (kt + 1) * BKH;
            const float* Wn = Wp + (kt + 1) * BKH;
            #pragma unroll
            for (int t = 0; t < 4; t++) {
                xa[t] = *(const float4*)(Xn + 4 * t);
                wb[t] = *(const float4*)(Wn + 4 * t);
            }
        }

        #pragma unroll
        for (int ks = 0; ks < 2; ks++) {
            uint32_t af[4][4], bf[2][4];
            #pragma unroll
            for (int i = 0; i < 4; i++) {
                const __half* p = &As[cur][(wm + 16 * i + (lane & 15)) * PAD
                                           + ks * 16 + ((lane >> 4) & 1) * 8];
                ldm_x4(af[i][0], af[i][1], af[i][2], af[i][3], smem_u32(p));
            }
            #pragma unroll
            for (int jj = 0; jj < 2; jj++) {
                int nrow = wn + jj * 16 + ((lane >> 4) & 1) * 8 + (lane & 7);
                int koff = ((lane >> 3) & 1) * 8;
                const __half* p = &Bs[cur][nrow * PAD + ks * 16 + koff];
                ldm_x4(bf[jj][0], bf[jj][1], bf[jj][2], bf[jj][3], smem_u32(p));
            }
            #pragma unroll
            for (int i = 0; i < 4; i++)
                #pragma unroll
                for (int j = 0; j < 4; j++)
                    mma16816(acc[i][j], af[i], &bf[j >> 1][(j & 1) * 2]);
        }

        __syncthreads();
        if (kt + 1 < NT) {
            sts_tile_f16(As[cur ^ 1], lrow, lcol, xa);
            sts_tile_f16(Bs[cur ^ 1], lrow, lcol, wb);
        }
        __syncthreads();
    }

    // epilogue
    const int frow = lane >> 2;
    const int fcol = (lane & 3) * 2;
    #pragma unroll
    for (int i = 0; i < 4; i++) {
        #pragma unroll
        for (int j = 0; j < 4; j++) {
            int n = n0 + wn + 8 * j + fcol;
            float b0 = bias[n], b1 = bias[n + 1];
            #pragma unroll
            for (int rr = 0; rr < 2; rr++) {
                int m = m0 + wm + 16 * i + frow + rr * 8;
                float v0 = acc[i][j][rr * 2 + 0] + b0;
                float v1 = acc[i][j][rr * 2 + 1] + b1;
                if (MODE == 0) {
                    int b_ = m >> 11, s_ = m & (SS - 1);
                    int h_ = n >> 6,  d_ = n & 63;
                    __half* Y = (__half*)Yv;
                    *reinterpret_cast<half2*>(
                        &Y[(((long)(b_ * HH + h_)) * SS + s_) * DKK + d_]) =
                        __floats2half2_rn(v0, v1);
                } else {
                    float* Y = (float*)Yv;
                    *reinterpret_cast<float2*>(&Y[(long)m * N + n]) =
                        make_float2(v0, v1);
                }
            }
        }
    }
}

// ---------------------------------------------------------------------------
// Tensor-core flash attention.
// Block: 128 queries of one (b,h). 8 warps x 16 query rows. 64-key chunks.
// QK^T and P@V on mma.m16n8k16; softmax in C-fragment registers (quad shfl).
// ---------------------------------------------------------------------------
#define AQT 128
#define AKT 64
#define APAD 72   // 144B rows: conflict-free ldmatrix

__global__ __launch_bounds__(256) void attention_mma_kernel(
    const __half* __restrict__ Q, const __half* __restrict__ K,
    const __half* __restrict__ V, float* __restrict__ O)
{
    __shared__ __half Qs[AQT * APAD];
    __shared__ __half Ks[AKT * APAD];
    __shared__ __half Vs[AKT * APAD];

    const int tid  = threadIdx.x;
    const int lane = tid & 31;
    const int wid  = tid >> 5;          // 0..7: query rows 16*wid..+15
    const int q0   = blockIdx.x * AQT;
    const int bh   = blockIdx.y;

    const __half* Qg = Q + ((long)bh * SS + q0) * DKK;
    const __half* Kg = K + (long)bh * SS * DKK;
    const __half* Vg = V + (long)bh * SS * DKK;

    // stage Q tile: 128 rows x 64 halfs (uint4 = 8 halfs)
    for (int t = tid; t < AQT * 8; t += 256) {
        int row = t >> 3, c = (t & 7) * 8;
        *(uint4*)&Qs[row * APAD + c] = *(const uint4*)(Qg + row * DKK + c);
    }
    __syncthreads();

    // Q fragments (loop-invariant): 4 k-steps of 16 over d=64
    uint32_t qf[4][4];
    #pragma unroll
    for (int ks = 0; ks < 4; ks++) {
        const __half* p = &Qs[(wid * 16 + (lane & 15)) * APAD
                              + ks * 16 + (lane >> 4) * 8];
        ldm_x4(qf[ks][0], qf[ks][1], qf[ks][2], qf[ks][3], smem_u32(p));
    }

    float m_i[2] = {-1e30f, -1e30f};
    float l_i[2] = {0.f, 0.f};
    float o[8][4];
    #pragma unroll
    for (int j = 0; j < 8; j++)
        #pragma unroll
        for (int c = 0; c < 4; c++) o[j][c] = 0.f;

    for (int kc = 0; kc < SS; kc += AKT) {
        __syncthreads();   // prior chunk's Ks/Vs reads done
        for (int t = tid; t < AKT * 8; t += 256) {
            int row = t >> 3, c = (t & 7) * 8;
            *(uint4*)&Ks[row * APAD + c] = *(const uint4*)(Kg + (long)(kc + row) * DKK + c);
            *(uint4*)&Vs[row * APAD + c] = *(const uint4*)(Vg + (long)(kc + row) * DKK + c);
        }
        __syncthreads();

        // ---- scores: S = Q K^T  (16 rows x 64 keys per warp) ----
        float s[8][4];
        #pragma unroll
        for (int j = 0; j < 8; j++)
            #pragma unroll
            for (int c = 0; c < 4; c++) s[j][c] = 0.f;

        #pragma unroll
        for (int j = 0; j < 8; j++) {         // key n-tile (8 keys)
            uint32_t bf[8];
            #pragma unroll
            for (int hf = 0; hf < 2; hf++) {  // d 0-31, 32-63
                const __half* p = &Ks[(8 * j + (lane & 7)) * APAD
                                      + 32 * hf + (lane >> 3) * 8];
                ldm_x4(bf[4*hf+0], bf[4*hf+1], bf[4*hf+2], bf[4*hf+3], smem_u32(p));
            }
            #pragma unroll
            for (int ks = 0; ks < 4; ks++)
                mma16816(s[j], qf[ks], &bf[2 * ks]);
        }

        // ---- online softmax in fragment registers ----
        float mx[2] = {-1e30f, -1e30f};
        #pragma unroll
        for (int j = 0; j < 8; j++) {
            #pragma unroll
            for (int c = 0; c < 2; c++) {
                s[j][c]     *= 0.125f;           // 1/sqrt(64)
                s[j][2 + c] *= 0.125f;
                mx[0] = fmaxf(mx[0], s[j][c]);
                mx[1] = fmaxf(mx[1], s[j][2 + c]);
            }
        }
        #pragma unroll
        for (int off = 1; off <= 2; off <<= 1) {
            mx[0] = fmaxf(mx[0], __shfl_xor_sync(0xffffffffu, mx[0], off));
            mx[1] = fmaxf(mx[1], __shfl_xor_sync(0xffffffffu, mx[1], off));
        }
        float nm0 = fmaxf(m_i[0], mx[0]);
        float nm1 = fmaxf(m_i[1], mx[1]);
        float corr0 = __expf(m_i[0] - nm0);
        float corr1 = __expf(m_i[1] - nm1);
        m_i[0] = nm0; m_i[1] = nm1;

        float sum0 = 0.f, sum1 = 0.f;
        #pragma unroll
        for (int j = 0; j < 8; j++) {
            #pragma unroll
            for (int c = 0; c < 2; c++) {
                float p0 = __expf(s[j][c]     - nm0);
                float p1 = __expf(s[j][2 + c] - nm1);
                s[j][c] = p0; s[j][2 + c] = p1;
                sum0 += p0; sum1 += p1;
            }
        }
        #pragma unroll
        for (int off = 1; off <= 2; off <<= 1) {
            sum0 += __shfl_xor_sync(0xffffffffu, sum0, off);
            sum1 += __shfl_xor_sync(0xffffffffu, sum1, off);
        }
        l_i[0] = l_i[0] * corr0 + sum0;
        l_i[1] = l_i[1] * corr1 + sum1;
        #pragma unroll
        for (int j = 0; j < 8; j++) {
            o[j][0] *= corr0; o[j][1] *= corr0;
            o[j][2] *= corr1; o[j][3] *= corr1;
        }

        // ---- P fragments straight from score fragments ----
        uint32_t pf[4][4];
        #pragma unroll
        for (int kt = 0; kt < 4; kt++) {
            half2 h;
            h = __floats2half2_rn(s[2*kt][0],   s[2*kt][1]);   pf[kt][0] = *(uint32_t*)&h;
            h = __floats2half2_rn(s[2*kt][2],   s[2*kt][3]);   pf[kt][1] = *(uint32_t*)&h;
            h = __floats2half2_rn(s[2*kt+1][0], s[2*kt+1][1]); pf[kt][2] = *(uint32_t*)&h;
            h = __floats2half2_rn(s[2*kt+1][2], s[2*kt+1][3]); pf[kt][3] = *(uint32_t*)&h;
        }

        // ---- O += P @ V  (V^T fragments via ldmatrix.trans) ----
        #pragma unroll
        for (int kt = 0; kt < 4; kt++) {        // key k-tile of 16
            #pragma unroll
            for (int ng = 0; ng < 4; ng++) {    // d group of 16
                uint32_t vf[4];
                const __half* p = &Vs[(16 * kt + (lane & 15)) * APAD
                                      + 16 * ng + (lane >> 4) * 8];
                ldm_x4_t(vf[0], vf[1], vf[2], vf[3], smem_u32(p));
                mma16816(o[2 * ng],     pf[kt], &vf[0]);
                mma16816(o[2 * ng + 1], pf[kt], &vf[2]);
            }
        }
    }

    // ---- finalize: write [B,S,Dmodel] fp32 ----
    const int b_ = bh >> 4;
    const int h_ = bh & 15;
    #pragma unroll
    for (int rr = 0; rr < 2; rr++) {
        float inv = 1.f / l_i[rr];
        int row = q0 + wid * 16 + (lane >> 2) + 8 * rr;
        float* Orow = O + ((long)b_ * SS + row) * DMODEL + h_ * DKK;
        #pragma unroll
        for (int j = 0; j < 8; j++) {
            int d = 8 * j + (lane & 3) * 2;
            *reinterpret_cast<float2*>(Orow + d) =
                make_float2(o[j][2 * rr] * inv, o[j][2 * rr + 1] * inv);
        }
    }
}

// ---------------------------------------------------------------------------
extern "C" void kernel_launch(void* const* d_in, const int* in_sizes, int n_in,
                              void* d_out, int out_size)
{
    const float* query = (const float*)d_in[0];
    const float* key   = (const float*)d_in[1];
    const float* value = (const float*)d_in[2];
    const float* w_q   = (const float*)d_in[3];
    const float* b_q   = (const float*)d_in[4];
    const float* w_k   = (const float*)d_in[5];
    const float* b_k   = (const float*)d_in[6];
    const float* w_v   = (const float*)d_in[7];
    const float* b_v   = (const float*)d_in[8];
    const float* w_o   = (const float*)d_in[9];
    const float* b_o   = (const float*)d_in[10];
    float* out = (float*)d_out;

    __half *q_buf, *k_buf, *v_buf;
    float* att_buf;
    cudaGetSymbolAddress((void**)&q_buf,   g_q);
    cudaGetSymbolAddress((void**)&k_buf,   g_k);
    cudaGetSymbolAddress((void**)&v_buf,   g_v);
    cudaGetSymbolAddress((void**)&att_buf, g_att);

    dim3 gGemm(DMODEL / BN, MTOT / BM);   // (8, 64)

    gemm_mma_kernel<0><<<gGemm, 256>>>(query, w_q, b_q, q_buf, MTOT, DMODEL, DMODEL);
    gemm_mma_kernel<0><<<gGemm, 256>>>(key,   w_k, b_k, k_buf, MTOT, DMODEL, DMODEL);
    gemm_mma_kernel<0><<<gGemm, 256>>>(value, w_v, b_v, v_buf, MTOT, DMODEL, DMODEL);

    attention_mma_kernel<<<dim3(SS / AQT, BB * HH), 256>>>(q_buf, k_buf, v_buf, att_buf);

    gemm_mma_kernel<1><<<gGemm, 256>>>(att_buf, w_o, b_o, out, MTOT, DMODEL, DMODEL);
}